// round 16
// baseline (speedup 1.0000x reference)
#include <cuda_runtime.h>
#include <cuda_fp16.h>
#include <math.h>
#include <stdint.h>

// ---------------------------------------------------------------------------
// Problem constants
// ---------------------------------------------------------------------------
#define BATCH   32
#define NTOK    255
#define NTOT    256
#define DIN     64
#define NHEAD   12
#define HID     768
#define FFN     3072
#define NLAYER  6
#define HDIM    64
#define MROWS   (BATCH*NTOT) // 8192
#define MATOM   (BATCH*NTOK) // 8160

// ---------------------------------------------------------------------------
// Scratch (device globals; no allocations allowed)
// ---------------------------------------------------------------------------
__device__ __align__(256) float  g_h  [(size_t)MROWS*HID];
__device__ __align__(256) __half g_yh [(size_t)MROWS*HID];
__device__ __align__(256) __half g_qh [(size_t)MROWS*HID];
__device__ __align__(256) __half g_kh [(size_t)MROWS*HID];
__device__ __align__(256) __half g_vh [(size_t)MROWS*HID];
__device__ __align__(256) __half g_oh [(size_t)MROWS*HID];
__device__ __align__(256) __half g_fh [(size_t)MROWS*FFN];
__device__ __align__(256) __half g_bias[(size_t)BATCH*NHEAD*NTOT*NTOT];

// fragment-packed fp16 weights (per layer: Wq,Wk,Wv,Wo,W1,W2 contiguous)
#define WT_QKVO (HID*HID)                  // halves
#define WT_L    (4*WT_QKVO + 2*HID*FFN)    // halves per layer
__device__ __align__(256) __half g_wt[(size_t)NLAYER*WT_L];

enum { EP_BIAS = 0, EP_BIAS_RES = 1, EP_BIAS_GELU = 2 };

// ---------------------------------------------------------------------------
// helpers
// ---------------------------------------------------------------------------
__device__ __forceinline__ void cp16(void* smem, const void* gmem) {
    unsigned s = (unsigned)__cvta_generic_to_shared(smem);
    asm volatile("cp.async.cg.shared.global [%0], [%1], 16;" :: "r"(s), "l"(gmem));
}
__device__ __forceinline__ void mmah(float c[4], const unsigned a[4],
                                     unsigned b0, unsigned b1) {
    asm volatile(
        "mma.sync.aligned.m16n8k16.row.col.f32.f16.f16.f32 "
        "{%0,%1,%2,%3}, {%4,%5,%6,%7}, {%8,%9}, {%0,%1,%2,%3};"
        : "+f"(c[0]), "+f"(c[1]), "+f"(c[2]), "+f"(c[3])
        : "r"(a[0]), "r"(a[1]), "r"(a[2]), "r"(a[3]), "r"(b0), "r"(b1));
}

// ---------------------------------------------------------------------------
// Weight repack: W[K][N] fp32 -> fragment-ordered fp16 half2 (per matrix)
// ---------------------------------------------------------------------------
__device__ __forceinline__ void repack_one(
    const float* __restrict__ in, __half2* __restrict__ out,
    unsigned idx, int N, int ktiles)
{
    const int c    = idx & 3;
    const int lane = (idx >> 2) & 31;
    const int p    = (idx >> 7) & 7;
    const unsigned rest = idx >> 10;
    const int kt = (int)(rest % (unsigned)ktiles);
    const int nt = (int)(rest / (unsigned)ktiles);
    const int g = lane >> 2, q = lane & 3;
    const int k = kt * 16 + (c & 1) * 8 + q * 2;
    const int n = nt * 128 + (p * 2 + (c >> 1)) * 8 + g;
    out[idx] = __floats2half2_rn(in[(size_t)k * N + n], in[(size_t)(k + 1) * N + n]);
}

__global__ __launch_bounds__(256) void repack_qkvo_kernel(
    const float* __restrict__ Wq, const float* __restrict__ Wk,
    const float* __restrict__ Wv, const float* __restrict__ Wo,
    __half2* __restrict__ wt)
{
    const int z = blockIdx.z, type = z & 3, layer = z >> 2;
    const float* ins[4] = { Wq, Wk, Wv, Wo };
    const float* in = ins[type] + (size_t)layer * HID * HID;
    __half2* out = wt + ((size_t)layer * WT_L + (size_t)type * WT_QKVO) / 2;
    repack_one(in, out, blockIdx.x * 256u + threadIdx.x, HID, HID / 16);
}

__global__ __launch_bounds__(256) void repack_w12_kernel(
    const float* __restrict__ W1, const float* __restrict__ W2,
    __half2* __restrict__ wt)
{
    const int z = blockIdx.z;
    const size_t szF = (size_t)HID * FFN;
    const unsigned idx = blockIdx.x * 256u + threadIdx.x;
    if (z < NLAYER) {
        const float* in = W1 + (size_t)z * szF;
        __half2* out = wt + ((size_t)z * WT_L + 4 * (size_t)WT_QKVO) / 2;
        repack_one(in, out, idx, FFN, HID / 16);
    } else {
        const int layer = z - NLAYER;
        const float* in = W2 + (size_t)layer * szF;
        __half2* out = wt + ((size_t)layer * WT_L + 4 * (size_t)WT_QKVO + szF) / 2;
        repack_one(in, out, idx, HID, FFN / 16);
    }
}

// ---------------------------------------------------------------------------
// Shared epilogue (TT = number of m16 tiles per warp: 2 -> 128-row CTA, 1 -> 64)
// ---------------------------------------------------------------------------
template<int MODE, bool OUTH, int TT>
__device__ __forceinline__ void hgemm_epilogue(
    float acc[TT][8][4], const float* bias, const float* R, void* Cout,
    int bm0, int bn0, int wm, int wn, int g, int q, int N)
{
    #pragma unroll
    for (int t = 0; t < TT; t++) {
        const int m0 = bm0 + wm + t * 16 + g;
        const int m1 = m0 + 8;
        #pragma unroll
        for (int j = 0; j < 8; j++) {
            const int n0 = bn0 + wn + j * 8 + q * 2;
            const float b0 = bias[n0], b1 = bias[n0 + 1];
            float v00 = acc[t][j][0] + b0;
            float v01 = acc[t][j][1] + b1;
            float v10 = acc[t][j][2] + b0;
            float v11 = acc[t][j][3] + b1;
            if (MODE == EP_BIAS_GELU) {
                v00 = 0.5f * v00 * (1.f + erff(v00 * 0.70710678118654752f));
                v01 = 0.5f * v01 * (1.f + erff(v01 * 0.70710678118654752f));
                v10 = 0.5f * v10 * (1.f + erff(v10 * 0.70710678118654752f));
                v11 = 0.5f * v11 * (1.f + erff(v11 * 0.70710678118654752f));
            }
            if (MODE == EP_BIAS_RES) {
                const float2 r0 = *reinterpret_cast<const float2*>(R + (size_t)m0 * N + n0);
                const float2 r1 = *reinterpret_cast<const float2*>(R + (size_t)m1 * N + n0);
                v00 += r0.x; v01 += r0.y; v10 += r1.x; v11 += r1.y;
            }
            if (OUTH) {
                __half2* C = (__half2*)Cout;
                C[((size_t)m0 * N + n0) >> 1] = __floats2half2_rn(v00, v01);
                C[((size_t)m1 * N + n0) >> 1] = __floats2half2_rn(v10, v11);
            } else {
                float* C = (float*)Cout;
                *reinterpret_cast<float2*>(C + (size_t)m0 * N + n0) = make_float2(v00, v01);
                *reinterpret_cast<float2*>(C + (size_t)m1 * N + n0) = make_float2(v10, v11);
            }
        }
    }
}

// ---------------------------------------------------------------------------
// hgemm16: K-chunk 16, 4-stage cp.async. CTA tile (TT*64) x 128.
// ---------------------------------------------------------------------------
template<int MODE, bool OUTH, bool QKV, int TT>
__global__ __launch_bounds__(256, 2) void hgemm16_kernel(
    const __half* __restrict__ A, const __half* __restrict__ Wpk,
    const float* __restrict__ bias0, const float* __restrict__ bias1,
    const float* __restrict__ bias2, const float* __restrict__ R,
    void* __restrict__ C0, void* __restrict__ C1, void* __restrict__ C2,
    int K, int N)
{
    __shared__ __half stA[4][TT * 64 * 24];
    __shared__ uint4  fgB[4][256];

    const int tid  = threadIdx.x;
    const int lane = tid & 31;
    const int warp = tid >> 5;
    const int g    = lane >> 2;
    const int q    = lane & 3;
    const int bm0  = blockIdx.y * (TT * 64);
    const int wn   = (warp & 1) * 64;
    const int wm   = (warp >> 1) * (TT * 16);

    int bn0 = blockIdx.x * 128;
    const float* bias = bias0;
    void* Cout = C0;
    if (QKV) {
        const int type = blockIdx.x / 6;         // 0=q 1=k 2=v
        bn0 -= type * 768;
        bias = (type == 0) ? bias0 : (type == 1 ? bias1 : bias2);
        Cout = (type == 0) ? C0 : (type == 1 ? C1 : C2);
    }

    const int nc = K / 16;
    const int arow = tid >> 1;
    const bool aact = (TT == 2) || (arow < 64);
    const __half* Ag = A + (size_t)(bm0 + arow) * K + (tid & 1) * 8;
    const uint4*  Bg = reinterpret_cast<const uint4*>(Wpk)
                       + (size_t)blockIdx.x * nc * 256 + tid;
    const int saOfs = arow * 24 + (tid & 1) * 8;

    float acc[TT][8][4];
    #pragma unroll
    for (int t = 0; t < TT; t++)
        #pragma unroll
        for (int j = 0; j < 8; j++)
            #pragma unroll
            for (int r = 0; r < 4; r++) acc[t][j][r] = 0.f;

    auto issue = [&](int s, int kt) {
        if (aact) cp16(&stA[s][saOfs], Ag + kt * 16);
        cp16(&fgB[s][tid], Bg + (size_t)kt * 256);
        asm volatile("cp.async.commit_group;");
    };

    issue(0, 0); issue(1, 1); issue(2, 2);

    for (int c = 0; c < nc; c++) {
        if (c <= nc - 3)      asm volatile("cp.async.wait_group 2;");
        else if (c == nc - 2) asm volatile("cp.async.wait_group 1;");
        else                  asm volatile("cp.async.wait_group 0;");
        __syncthreads();
        if (c + 3 < nc) issue((c + 3) & 3, c + 3);

        const int buf = c & 3;
        unsigned a[TT][4];
        #pragma unroll
        for (int t = 0; t < TT; t++) {
            const __half* st = &stA[buf][(wm + t * 16 + g) * 24 + 2 * q];
            a[t][0] = *reinterpret_cast<const unsigned*>(st);
            a[t][1] = *reinterpret_cast<const unsigned*>(st + 8 * 24);
            a[t][2] = *reinterpret_cast<const unsigned*>(st + 8);
            a[t][3] = *reinterpret_cast<const unsigned*>(st + 8 * 24 + 8);
        }
        #pragma unroll
        for (int jp = 0; jp < 4; jp++) {
            const uint4 v = fgB[buf][((warp & 1) * 4 + jp) * 32 + lane];
            #pragma unroll
            for (int t = 0; t < TT; t++) {
                mmah(acc[t][jp * 2    ], a[t], v.x, v.y);
                mmah(acc[t][jp * 2 + 1], a[t], v.z, v.w);
            }
        }
    }

    hgemm_epilogue<MODE, OUTH, TT>(acc, bias, R, Cout, bm0, bn0, wm, wn, g, q, N);
}

// ---------------------------------------------------------------------------
// hgemm32: K-chunk 32, 3-stage. CTA tile (TT*64) x 128.
// ---------------------------------------------------------------------------
#define ASTRIDE 40

template<int MODE, bool OUTH, int TT>
__global__ __launch_bounds__(256, 2) void hgemm32_kernel(
    const __half* __restrict__ A, const __half* __restrict__ Wpk,
    const float* __restrict__ bias, const float* __restrict__ R,
    void* __restrict__ Cout, int K, int N)
{
    extern __shared__ char hsm[];
    __half* stA = (__half*)hsm;                                  // [3][TT*64*40]
    uint4*  fgB = (uint4*)(hsm + 3 * TT * 64 * ASTRIDE * 2);     // [3][512]

    const int tid  = threadIdx.x;
    const int lane = tid & 31;
    const int warp = tid >> 5;
    const int g    = lane >> 2;
    const int q    = lane & 3;
    const int bm0  = blockIdx.y * (TT * 64);
    const int bn0  = blockIdx.x * 128;
    const int wn   = (warp & 1) * 64;
    const int wm   = (warp >> 1) * (TT * 16);

    const int nc = K / 32;
    const __half* Ag = A + (size_t)(bm0 + (tid >> 2)) * K + (tid & 3) * 8;
    const uint4*  Bg = reinterpret_cast<const uint4*>(Wpk)
                       + (size_t)blockIdx.x * (K / 16) * 256 + tid;
    const int saOfs = (tid >> 2) * ASTRIDE + (tid & 3) * 8;

    float acc[TT][8][4];
    #pragma unroll
    for (int t = 0; t < TT; t++)
        #pragma unroll
        for (int j = 0; j < 8; j++)
            #pragma unroll
            for (int r = 0; r < 4; r++) acc[t][j][r] = 0.f;

    auto issue = [&](int s, int kt) {
        __half* sa = stA + s * (TT * 64 * ASTRIDE);
        cp16(sa + saOfs, Ag + kt * 32);
        if (TT == 2)
            cp16(sa + saOfs + 64 * ASTRIDE, Ag + (size_t)64 * K + kt * 32);
        uint4* fb = fgB + s * 512;
        cp16(fb + tid,       Bg + (size_t)kt * 512);
        cp16(fb + tid + 256, Bg + (size_t)kt * 512 + 256);
        asm volatile("cp.async.commit_group;");
    };

    issue(0, 0); issue(1, 1);

    for (int c = 0; c < nc; c++) {
        if (c < nc - 1) asm volatile("cp.async.wait_group 1;");
        else            asm volatile("cp.async.wait_group 0;");
        __syncthreads();
        if (c + 2 < nc) {
            int s = c + 2; s -= (s >= 3) ? ((s / 3) * 3) : 0;
            issue(s, c + 2);
        }

        int buf = c; buf -= (buf / 3) * 3;
        const __half* sa = stA + buf * (TT * 64 * ASTRIDE);
        const uint4*  fb = fgB + buf * 512;

        #pragma unroll
        for (int s = 0; s < 2; s++) {
            unsigned a[TT][4];
            #pragma unroll
            for (int t = 0; t < TT; t++) {
                const __half* st = sa + (wm + t * 16 + g) * ASTRIDE + s * 16 + 2 * q;
                a[t][0] = *reinterpret_cast<const unsigned*>(st);
                a[t][1] = *reinterpret_cast<const unsigned*>(st + 8 * ASTRIDE);
                a[t][2] = *reinterpret_cast<const unsigned*>(st + 8);
                a[t][3] = *reinterpret_cast<const unsigned*>(st + 8 * ASTRIDE + 8);
            }
            #pragma unroll
            for (int jp = 0; jp < 4; jp++) {
                const uint4 v = fb[s * 256 + ((warp & 1) * 4 + jp) * 32 + lane];
                #pragma unroll
                for (int t = 0; t < TT; t++) {
                    mmah(acc[t][jp * 2    ], a[t], v.x, v.y);
                    mmah(acc[t][jp * 2 + 1], a[t], v.z, v.w);
                }
            }
        }
    }

    hgemm_epilogue<MODE, OUTH, TT>(acc, bias, R, Cout, bm0, bn0, wm, wn, g, q, N);
}

#define HG32_SMEM(TT) (3*((TT)*64*ASTRIDE*2) + 3*512*16)

// ---------------------------------------------------------------------------
// fused: atom-encoder SGEMM (x<6) + structural bias (fp16) + token fill
// ---------------------------------------------------------------------------
#define BM 128
#define BN 128
#define BK 8
#define TM 8
#define TN 8
#define XTRA 1538u

__global__ __launch_bounds__(256) void atom_fused_kernel(
    const float* __restrict__ A, const float* __restrict__ W,
    const float* __restrict__ bias_b, float* __restrict__ C,
    const int* __restrict__ len_spd, const float* __restrict__ spd_emb,
    const float* __restrict__ virt, const float* __restrict__ gt,
    __half* __restrict__ bias)
{
    const int tid = threadIdx.x;

    if (blockIdx.x >= 6) {
        const size_t idx = ((size_t)(blockIdx.x - 6) * 64 + blockIdx.y) * 256 + tid;
        const size_t btot = (size_t)BATCH * NHEAD * NTOT * NTOT;
        if (idx < btot) {
            const int j = (int)(idx & 255);
            const int i = (int)((idx >> 8) & 255);
            const int hh = (int)((idx >> 16) % NHEAD);
            const int b = (int)(idx / ((size_t)NHEAD * NTOT * NTOT));
            float v;
            if (i == 0 || j == 0) {
                v = virt[hh];
            } else {
                const int lsp = len_spd[((size_t)b * NTOK + (i - 1)) * NTOK + (j - 1)];
                v = (lsp == 0) ? 0.f : spd_emb[lsp * NHEAD + hh];
            }
            bias[idx] = __float2half_rn(v);
        } else {
            const size_t r = idx - btot;
            if (r < (size_t)BATCH * HID) {
                const int b = (int)(r / HID), t = (int)(r % HID);
                C[(size_t)b * NTOT * HID + t] = gt[t];
            }
        }
        return;
    }

    __shared__ float As[BK][BM];
    __shared__ float Bs[BK][BN];

    const int bm0 = blockIdx.y * BM;
    const int bn0 = blockIdx.x * BN;
    const int tx = tid & 15;
    const int ty = tid >> 4;

    float acc[TM][TN];
    #pragma unroll
    for (int i = 0; i < TM; i++)
        #pragma unroll
        for (int j = 0; j < TN; j++) acc[i][j] = 0.f;

    const int arow = tid >> 1;
    const int acol = (tid & 1) * 4;
    const int brow = tid >> 5;
    const int bcol = (tid & 31) * 4;

    for (int k0 = 0; k0 < DIN; k0 += BK) {
        float4 av;
        const int gm = bm0 + arow;
        if (gm < MATOM)
            av = *reinterpret_cast<const float4*>(A + (size_t)gm * DIN + k0 + acol);
        else
            av = make_float4(0.f, 0.f, 0.f, 0.f);
        As[acol + 0][arow] = av.x;
        As[acol + 1][arow] = av.y;
        As[acol + 2][arow] = av.z;
        As[acol + 3][arow] = av.w;

        const float4 bv = *reinterpret_cast<const float4*>(
            W + (size_t)(k0 + brow) * HID + bn0 + bcol);
        *reinterpret_cast<float4*>(&Bs[brow][bcol]) = bv;

        __syncthreads();
        #pragma unroll
        for (int k = 0; k < BK; k++) {
            float af[TM], bf[TN];
            #pragma unroll
            for (int i = 0; i < TM; i++) af[i] = As[k][ty * TM + i];
            #pragma unroll
            for (int j = 0; j < TN; j++) bf[j] = Bs[k][tx * TN + j];
            #pragma unroll
            for (int i = 0; i < TM; i++)
                #pragma unroll
                for (int j = 0; j < TN; j++)
                    acc[i][j] = fmaf(af[i], bf[j], acc[i][j]);
        }
        __syncthreads();
    }

    #pragma unroll
    for (int i = 0; i < TM; i++) {
        const int m = bm0 + ty * TM + i;
        if (m >= MATOM) continue;
        const size_t orow = (size_t)m + (size_t)(m / NTOK) + 1;
        #pragma unroll
        for (int j = 0; j < TN; j++) {
            const int nn = bn0 + tx * TN + j;
            C[orow * HID + nn] = acc[i][j] + bias_b[nn];
        }
    }
}

// ---------------------------------------------------------------------------
// LayerNorm v2: warp-per-row, grid-stride, shfl-only reductions, no smem.
// ---------------------------------------------------------------------------
#define LN_BLOCKS 256

template<bool OUTH>
__global__ __launch_bounds__(256) void ln_kernel(
    const float* __restrict__ X, const float* __restrict__ w,
    const float* __restrict__ b, void* __restrict__ Yout)
{
    const int lane = threadIdx.x & 31;
    const int gw0  = blockIdx.x * 8 + (threadIdx.x >> 5);

    for (int row = gw0; row < MROWS; row += LN_BLOCKS * 8) {
        const float* x = X + (size_t)row * HID;
        float v[24];
        float s = 0.f;
        #pragma unroll
        for (int i = 0; i < 24; i++) { v[i] = x[lane + 32 * i]; s += v[i]; }
        #pragma unroll
        for (int o = 16; o > 0; o >>= 1) s += __shfl_xor_sync(~0u, s, o);
        const float mu = s * (1.f / HID);

        float s2 = 0.f;
        #pragma unroll
        for (int i = 0; i < 24; i++) { const float d = v[i] - mu; s2 = fmaf(d, d, s2); }
        #pragma unroll
        for (int o = 16; o > 0; o >>= 1) s2 += __shfl_xor_sync(~0u, s2, o);
        const float inv = rsqrtf(s2 * (1.f / HID) + 1e-5f);

        if (OUTH) {
            __half* Y = (__half*)Yout + (size_t)row * HID;
            #pragma unroll
            for (int i = 0; i < 24; i++) {
                const int c = lane + 32 * i;
                Y[c] = __float2half_rn((v[i] - mu) * inv * w[c] + b[c]);
            }
        } else {
            float* Y = (float*)Yout + (size_t)row * HID;
            #pragma unroll
            for (int i = 0; i < 24; i++) {
                const int c = lane + 32 * i;
                Y[c] = (v[i] - mu) * inv * w[c] + b[c];
            }
        }
    }
}

// ---------------------------------------------------------------------------
// Attention v3 (256 threads, __expf, fp16 bias) — frozen.
// ---------------------------------------------------------------------------
#define KT_S 264
#define VT_S 72
#define QS_S 36
#define ATTN_SMEM ((32*KT_S + 128*VT_S + 128*QS_S) * 4)

__global__ __launch_bounds__(256, 1) void attn_kernel(
    const __half* __restrict__ Q, const __half* __restrict__ K,
    const __half* __restrict__ V, const __half* __restrict__ bias,
    __half* __restrict__ O)
{
    extern __shared__ char smraw[];
    __half2* KT = (__half2*)smraw;
    __half2* VT = KT + 32 * KT_S;
    __half2* QS = VT + 128 * VT_S;

    const int h = blockIdx.x, b = blockIdx.y;
    const int tid = threadIdx.x, lane = tid & 31, warp = tid >> 5;
    const int g = lane >> 2, q = lane & 3;
    const size_t base = (size_t)b * NTOT * HID + (size_t)h * HDIM;

    for (int i = tid; i < 8192; i += 256) {
        const int n = i >> 5, k2 = i & 31;
        KT[k2 * KT_S + n] =
            reinterpret_cast<const __half2*>(K + base + (size_t)n * HID)[k2];
    }
    for (int i = tid; i < 8192; i += 256) {
        const int t2 = i >> 6, d = i & 63;
        VT[t2 * VT_S + d] = __halves2half2(V[base + (size_t)(2 * t2) * HID + d],
                                           V[base + (size_t)(2 * t2 + 1) * HID + d]);
    }

    const __half* bb = bias + (((size_t)b * NHEAD + h) * NTOT) * NTOT;

    for (int pass = 0; pass < 2; pass++) {
        __syncthreads();
        for (int i = tid; i < 4096; i += 256) {
            const int r = i >> 5, k2 = i & 31;
            QS[r * QS_S + k2] = reinterpret_cast<const __half2*>(
                Q + base + (size_t)(pass * 128 + r) * HID)[k2];
        }
        __syncthreads();

        const int r0 = warp * 16;
        float sc[32][4];
        #pragma unroll
        for (int j = 0; j < 32; j++) {
            sc[j][0] = sc[j][1] = sc[j][2] = sc[j][3] = 0.f;
        }

        #pragma unroll
        for (int kt = 0; kt < 4; kt++) {
            unsigned a[4];
            a[0] = *reinterpret_cast<const unsigned*>(&QS[(r0 + g    ) * QS_S + q + 8 * kt]);
            a[1] = *reinterpret_cast<const unsigned*>(&QS[(r0 + g + 8) * QS_S + q + 8 * kt]);
            a[2] = *reinterpret_cast<const unsigned*>(&QS[(r0 + g    ) * QS_S + q + 4 + 8 * kt]);
            a[3] = *reinterpret_cast<const unsigned*>(&QS[(r0 + g + 8) * QS_S + q + 4 + 8 * kt]);
            #pragma unroll
            for (int j = 0; j < 32; j++) {
                const unsigned b0 = *reinterpret_cast<const unsigned*>(
                    &KT[(8 * kt + q    ) * KT_S + j * 8 + g]);
                const unsigned b1 = *reinterpret_cast<const unsigned*>(
                    &KT[(8 * kt + 4 + q) * KT_S + j * 8 + g]);
                mmah(sc[j], a, b0, b1);
            }
        }

        const int qi0 = pass * 128 + r0 + g;
        const int qi1 = qi0 + 8;
        const __half* b0r = bb + (size_t)qi0 * NTOT;
        const __half* b1r = bb + (size_t)qi1 * NTOT;

        float m0 = -1e30f, m1 = -1e30f;
        #pragma unroll
        for (int j = 0; j < 32; j++) {
            const float2 bg0 = __half22float2(
                *reinterpret_cast<const __half2*>(&b0r[j * 8 + 2 * q]));
            const float2 bg1 = __half22float2(
                *reinterpret_cast<const __half2*>(&b1r[j * 8 + 2 * q]));
            sc[j][0] = sc[j][0] * 0.125f + bg0.x;
            sc[j][1] = sc[j][1] * 0.125f + bg0.y;
            sc[j][2] = sc[j][2] * 0.125f + bg1.x;
            sc[j][3] = sc[j][3] * 0.125f + bg1.y;
            m0 = fmaxf(m0, fmaxf(sc[j][0], sc[j][1]));
            m1 = fmaxf(m1, fmaxf(sc[j][2], sc[j][3]));
        }
        m0 = fmaxf(m0, __shfl_xor_sync(~0u, m0, 1));
        m0 = fmaxf(m0, __shfl_xor_sync(~0u, m0, 2));
        m1 = fmaxf(m1, __shfl_xor_sync(~0u, m1, 1));
        m1 = fmaxf(m1, __shfl_xor_sync(~0u, m1, 2));

        float s0 = 0.f, s1 = 0.f;
        unsigned p0[32], p1[32];
        #pragma unroll
        for (int j = 0; j < 32; j++) {
            const float e0 = __expf(sc[j][0] - m0), e1 = __expf(sc[j][1] - m0);
            const float e2 = __expf(sc[j][2] - m1), e3 = __expf(sc[j][3] - m1);
            s0 += e0 + e1; s1 += e2 + e3;
            const __half2 h0 = __floats2half2_rn(e0, e1);
            const __half2 h1 = __floats2half2_rn(e2, e3);
            p0[j] = *reinterpret_cast<const unsigned*>(&h0);
            p1[j] = *reinterpret_cast<const unsigned*>(&h1);
        }
        s0 += __shfl_xor_sync(~0u, s0, 1); s0 += __shfl_xor_sync(~0u, s0, 2);
        s1 += __shfl_xor_sync(~0u, s1, 1); s1 += __shfl_xor_sync(~0u, s1, 2);
        const float i0 = 1.f / s0, i1 = 1.f / s1;

        float av[8][4];
        #pragma unroll
        for (int j = 0; j < 8; j++) {
            av[j][0] = av[j][1] = av[j][2] = av[j][3] = 0.f;
        }
        #pragma unroll
        for (int kt = 0; kt < 16; kt++) {
            const unsigned a[4] = { p0[2 * kt], p1[2 * kt], p0[2 * kt + 1], p1[2 * kt + 1] };
            #pragma unroll
            for (int j = 0; j < 8; j++) {
                const unsigned vb0 = *reinterpret_cast<const unsigned*>(
                    &VT[(8 * kt + q    ) * VT_S + j * 8 + g]);
                const unsigned vb1 = *reinterpret_cast<const unsigned*>(
                    &VT[(8 * kt + 4 + q) * VT_S + j * 8 + g]);
                mmah(av[j], a, vb0, vb1);
            }
        }

        __half2* O0 = reinterpret_cast<__half2*>(O + base + (size_t)qi0 * HID);
        __half2* O1 = reinterpret_cast<__half2*>(O + base + (size_t)qi1 * HID);
        #pragma unroll
        for (int j = 0; j < 8; j++) {
            O0[j * 4 + q] = __floats2half2_rn(av[j][0] * i0, av[j][1] * i0);
            O1[j * 4 + q] = __floats2half2_rn(av[j][2] * i1, av[j][3] * i1);
        }
    }
}

// ---------------------------------------------------------------------------
// Launch
// ---------------------------------------------------------------------------
extern "C" void kernel_launch(void* const* d_in, const int* in_sizes, int n_in,
                              void* d_out, int out_size)
{
    const float* x          = (const float*)d_in[0];
    const int*   len_spd    = (const int*)  d_in[1];
    const float* atom_W     = (const float*)d_in[2];
    const float* atom_b     = (const float*)d_in[3];
    const float* spd_emb    = (const float*)d_in[4];
    const float* graph_tok  = (const float*)d_in[5];
    const float* virt_dist  = (const float*)d_in[6];
    const float* ln1_w      = (const float*)d_in[7];
    const float* ln1_b      = (const float*)d_in[8];
    const float* Wq         = (const float*)d_in[9];
    const float* bq         = (const float*)d_in[10];
    const float* Wk         = (const float*)d_in[11];
    const float* bk         = (const float*)d_in[12];
    const float* Wv         = (const float*)d_in[13];
    const float* bv         = (const float*)d_in[14];
    const float* Wo         = (const float*)d_in[15];
    const float* bo         = (const float*)d_in[16];
    const float* ln2_w      = (const float*)d_in[17];
    const float* ln2_b      = (const float*)d_in[18];
    const float* W1         = (const float*)d_in[19];
    const float* b1         = (const float*)d_in[20];
    const float* W2         = (const float*)d_in[21];
    const float* b2         = (const float*)d_in[22];
    const float* fln_w      = (const float*)d_in[23];
    const float* fln_b      = (const float*)d_in[24];

    float *h;
    __half *yh, *qh, *kh, *vh, *oh, *fh, *wt, *bias;
    cudaGetSymbolAddress((void**)&h,    g_h);
    cudaGetSymbolAddress((void**)&yh,   g_yh);
    cudaGetSymbolAddress((void**)&qh,   g_qh);
    cudaGetSymbolAddress((void**)&kh,   g_kh);
    cudaGetSymbolAddress((void**)&vh,   g_vh);
    cudaGetSymbolAddress((void**)&oh,   g_oh);
    cudaGetSymbolAddress((void**)&fh,   g_fh);
    cudaGetSymbolAddress((void**)&bias, g_bias);
    cudaGetSymbolAddress((void**)&wt,   g_wt);

    cudaFuncSetAttribute(attn_kernel, cudaFuncAttributeMaxDynamicSharedMemorySize,
                         (int)ATTN_SMEM);
    cudaFuncSetAttribute(hgemm32_kernel<EP_BIAS_RES, false, 1>,
                         cudaFuncAttributeMaxDynamicSharedMemorySize, HG32_SMEM(1));

    const size_t szQ = (size_t)HID * HID, szF = (size_t)HID * FFN;

    const dim3 gQKV(18, MROWS / 128);      // TT=2
    const dim3 gHID64(HID / 128, MROWS / 64);  // TT=1: 6 x 128
    const dim3 gFFN(FFN / 128, MROWS / 128);   // TT=2

    // L1: repack QKVO weights (all layers)
    repack_qkvo_kernel<<<dim3((unsigned)(szQ / 2 / 256), 1, 4 * NLAYER), 256>>>(
        Wq, Wk, Wv, Wo, (__half2*)wt);
    // L2: fused atom encoder + bias(fp16) + token fill
    atom_fused_kernel<<<dim3(6 + XTRA, 64), 256>>>(
        x, atom_W, atom_b, h, len_spd, spd_emb, virt_dist, graph_tok, bias);
    // L3: ln1 layer 0
    ln_kernel<true><<<LN_BLOCKS, 256>>>(h, ln1_w, ln1_b, yh);
    // L4: QKV fused hgemm16 layer 0  <-- ncu capture slot
    hgemm16_kernel<EP_BIAS, true, true, 2><<<gQKV, 256>>>(
        yh, wt, bq, bk, bv, nullptr, qh, kh, vh, HID, HID);
    // L5: repack W1/W2
    repack_w12_kernel<<<dim3((unsigned)(szF / 2 / 256), 1, 2 * NLAYER), 256>>>(
        W1, W2, (__half2*)wt);

    for (int l = 0; l < NLAYER; l++) {
        const size_t bofs  = (size_t)l * HID;
        const size_t b1ofs = (size_t)l * FFN;
        __half* wl = wt + (size_t)l * WT_L;

        if (l > 0) {
            ln_kernel<true><<<LN_BLOCKS, 256>>>(h, ln1_w + bofs, ln1_b + bofs, yh);
            hgemm16_kernel<EP_BIAS, true, true, 2><<<gQKV, 256>>>(
                yh, wl, bq + bofs, bk + bofs, bv + bofs, nullptr,
                qh, kh, vh, HID, HID);
        }

        attn_kernel<<<dim3(NHEAD, BATCH), 256, ATTN_SMEM>>>(qh, kh, vh, bias, oh);

        // O-proj: M64 tile (wave packing)
        hgemm16_kernel<EP_BIAS_RES, false, false, 1><<<gHID64, 256>>>(
            oh, wl + 3 * (size_t)WT_QKVO, bo + bofs, nullptr, nullptr, h,
            h, nullptr, nullptr, HID, HID);

        ln_kernel<true><<<LN_BLOCKS, 256>>>(h, ln2_w + bofs, ln2_b + bofs, yh);

        hgemm16_kernel<EP_BIAS_GELU, true, false, 2><<<gFFN, 256>>>(
            yh, wl + 4 * (size_t)WT_QKVO, b1 + b1ofs, nullptr, nullptr, nullptr,
            fh, nullptr, nullptr, HID, FFN);
        // FFN2: M64 tile (wave packing), K-chunk 32
        hgemm32_kernel<EP_BIAS_RES, false, 1><<<gHID64, 256, HG32_SMEM(1)>>>(
            fh, wl + 4 * (size_t)WT_QKVO + szF, b2 + bofs, h,
            h, FFN, HID);
    }

    ln_kernel<false><<<LN_BLOCKS, 256>>>(h, fln_w, fln_b, d_out);
}

// round 17
// speedup vs baseline: 1.0609x; 1.0609x over previous
#include <cuda_runtime.h>
#include <cuda_fp16.h>
#include <math.h>
#include <stdint.h>

// ---------------------------------------------------------------------------
// Problem constants
// ---------------------------------------------------------------------------
#define BATCH   32
#define NTOK    255
#define NTOT    256
#define DIN     64
#define NHEAD   12
#define HID     768
#define FFN     3072
#define NLAYER  6
#define HDIM    64
#define MROWS   (BATCH*NTOT) // 8192
#define MATOM   (BATCH*NTOK) // 8160

// ---------------------------------------------------------------------------
// Scratch (device globals; no allocations allowed)
// ---------------------------------------------------------------------------
__device__ __align__(256) float  g_h  [(size_t)MROWS*HID];
__device__ __align__(256) __half g_yh [(size_t)MROWS*HID];
__device__ __align__(256) __half g_qh [(size_t)MROWS*HID];
__device__ __align__(256) __half g_kh [(size_t)MROWS*HID];
__device__ __align__(256) __half g_vh [(size_t)MROWS*HID];
__device__ __align__(256) __half g_oh [(size_t)MROWS*HID];
__device__ __align__(256) __half g_fh [(size_t)MROWS*FFN];
__device__ __align__(256) __half g_bias[(size_t)BATCH*NHEAD*NTOT*NTOT];

// fragment-packed fp16 weights (per layer: Wq,Wk,Wv,Wo,W1,W2 contiguous)
#define WT_QKVO (HID*HID)                  // halves
#define WT_L    (4*WT_QKVO + 2*HID*FFN)    // halves per layer
__device__ __align__(256) __half g_wt[(size_t)NLAYER*WT_L];

enum { EP_BIAS = 0, EP_BIAS_RES = 1, EP_BIAS_GELU = 2 };

// ---------------------------------------------------------------------------
// helpers
// ---------------------------------------------------------------------------
__device__ __forceinline__ void cp16(void* smem, const void* gmem) {
    unsigned s = (unsigned)__cvta_generic_to_shared(smem);
    asm volatile("cp.async.cg.shared.global [%0], [%1], 16;" :: "r"(s), "l"(gmem));
}
__device__ __forceinline__ void mmah(float c[4], const unsigned a[4],
                                     unsigned b0, unsigned b1) {
    asm volatile(
        "mma.sync.aligned.m16n8k16.row.col.f32.f16.f16.f32 "
        "{%0,%1,%2,%3}, {%4,%5,%6,%7}, {%8,%9}, {%0,%1,%2,%3};"
        : "+f"(c[0]), "+f"(c[1]), "+f"(c[2]), "+f"(c[3])
        : "r"(a[0]), "r"(a[1]), "r"(a[2]), "r"(a[3]), "r"(b0), "r"(b1));
}

// ---------------------------------------------------------------------------
// Weight repack: W[K][N] fp32 -> fragment-ordered fp16 half2 (per matrix)
// ---------------------------------------------------------------------------
__device__ __forceinline__ void repack_one(
    const float* __restrict__ in, __half2* __restrict__ out,
    unsigned idx, int N, int ktiles)
{
    const int c    = idx & 3;
    const int lane = (idx >> 2) & 31;
    const int p    = (idx >> 7) & 7;
    const unsigned rest = idx >> 10;
    const int kt = (int)(rest % (unsigned)ktiles);
    const int nt = (int)(rest / (unsigned)ktiles);
    const int g = lane >> 2, q = lane & 3;
    const int k = kt * 16 + (c & 1) * 8 + q * 2;
    const int n = nt * 128 + (p * 2 + (c >> 1)) * 8 + g;
    out[idx] = __floats2half2_rn(in[(size_t)k * N + n], in[(size_t)(k + 1) * N + n]);
}

__global__ __launch_bounds__(256) void repack_qkvo_kernel(
    const float* __restrict__ Wq, const float* __restrict__ Wk,
    const float* __restrict__ Wv, const float* __restrict__ Wo,
    __half2* __restrict__ wt)
{
    const int z = blockIdx.z, type = z & 3, layer = z >> 2;
    const float* ins[4] = { Wq, Wk, Wv, Wo };
    const float* in = ins[type] + (size_t)layer * HID * HID;
    __half2* out = wt + ((size_t)layer * WT_L + (size_t)type * WT_QKVO) / 2;
    repack_one(in, out, blockIdx.x * 256u + threadIdx.x, HID, HID / 16);
}

__global__ __launch_bounds__(256) void repack_w12_kernel(
    const float* __restrict__ W1, const float* __restrict__ W2,
    __half2* __restrict__ wt)
{
    const int z = blockIdx.z;
    const size_t szF = (size_t)HID * FFN;
    const unsigned idx = blockIdx.x * 256u + threadIdx.x;
    if (z < NLAYER) {
        const float* in = W1 + (size_t)z * szF;
        __half2* out = wt + ((size_t)z * WT_L + 4 * (size_t)WT_QKVO) / 2;
        repack_one(in, out, idx, FFN, HID / 16);
    } else {
        const int layer = z - NLAYER;
        const float* in = W2 + (size_t)layer * szF;
        __half2* out = wt + ((size_t)layer * WT_L + 4 * (size_t)WT_QKVO + szF) / 2;
        repack_one(in, out, idx, HID, FFN / 16);
    }
}

// ---------------------------------------------------------------------------
// Shared epilogue
// ---------------------------------------------------------------------------
template<int MODE, bool OUTH>
__device__ __forceinline__ void hgemm_epilogue(
    float acc[2][8][4], const float* bias, const float* R, void* Cout,
    int bm0, int bn0, int wm, int wn, int g, int q, int N)
{
    #pragma unroll
    for (int t = 0; t < 2; t++) {
        const int m0 = bm0 + wm + t * 16 + g;
        const int m1 = m0 + 8;
        #pragma unroll
        for (int j = 0; j < 8; j++) {
            const int n0 = bn0 + wn + j * 8 + q * 2;
            const float b0 = bias[n0], b1 = bias[n0 + 1];
            float v00 = acc[t][j][0] + b0;
            float v01 = acc[t][j][1] + b1;
            float v10 = acc[t][j][2] + b0;
            float v11 = acc[t][j][3] + b1;
            if (MODE == EP_BIAS_GELU) {
                v00 = 0.5f * v00 * (1.f + erff(v00 * 0.70710678118654752f));
                v01 = 0.5f * v01 * (1.f + erff(v01 * 0.70710678118654752f));
                v10 = 0.5f * v10 * (1.f + erff(v10 * 0.70710678118654752f));
                v11 = 0.5f * v11 * (1.f + erff(v11 * 0.70710678118654752f));
            }
            if (MODE == EP_BIAS_RES) {
                const float2 r0 = *reinterpret_cast<const float2*>(R + (size_t)m0 * N + n0);
                const float2 r1 = *reinterpret_cast<const float2*>(R + (size_t)m1 * N + n0);
                v00 += r0.x; v01 += r0.y; v10 += r1.x; v11 += r1.y;
            }
            if (OUTH) {
                __half2* C = (__half2*)Cout;
                C[((size_t)m0 * N + n0) >> 1] = __floats2half2_rn(v00, v01);
                C[((size_t)m1 * N + n0) >> 1] = __floats2half2_rn(v10, v11);
            } else {
                float* C = (float*)Cout;
                *reinterpret_cast<float2*>(C + (size_t)m0 * N + n0) = make_float2(v00, v01);
                *reinterpret_cast<float2*>(C + (size_t)m1 * N + n0) = make_float2(v10, v11);
            }
        }
    }
}

// ---------------------------------------------------------------------------
// hgemm16: K-chunk 16, 4-stage cp.async (K=768 GEMMs). CTA 128x128.
// ---------------------------------------------------------------------------
template<int MODE, bool OUTH, bool QKV>
__global__ __launch_bounds__(256, 2) void hgemm16_kernel(
    const __half* __restrict__ A, const __half* __restrict__ Wpk,
    const float* __restrict__ bias0, const float* __restrict__ bias1,
    const float* __restrict__ bias2, const float* __restrict__ R,
    void* __restrict__ C0, void* __restrict__ C1, void* __restrict__ C2,
    int K, int N)
{
    __shared__ __half stA[4][128 * 24];
    __shared__ uint4  fgB[4][256];

    const int tid  = threadIdx.x;
    const int lane = tid & 31;
    const int warp = tid >> 5;
    const int g    = lane >> 2;
    const int q    = lane & 3;
    const int bm0  = blockIdx.y * 128;
    const int wn   = (warp & 1) * 64;
    const int wm   = (warp >> 1) * 32;

    int bn0 = blockIdx.x * 128;
    const float* bias = bias0;
    void* Cout = C0;
    if (QKV) {
        const int type = blockIdx.x / 6;         // 0=q 1=k 2=v
        bn0 -= type * 768;
        bias = (type == 0) ? bias0 : (type == 1 ? bias1 : bias2);
        Cout = (type == 0) ? C0 : (type == 1 ? C1 : C2);
    }

    const int nc = K / 16;
    const __half* Ag = A + (size_t)(bm0 + (tid >> 1)) * K + (tid & 1) * 8;
    const uint4*  Bg = reinterpret_cast<const uint4*>(Wpk)
                       + (size_t)blockIdx.x * nc * 256 + tid;
    const int saOfs = (tid >> 1) * 24 + (tid & 1) * 8;

    float acc[2][8][4];
    #pragma unroll
    for (int t = 0; t < 2; t++)
        #pragma unroll
        for (int j = 0; j < 8; j++)
            #pragma unroll
            for (int r = 0; r < 4; r++) acc[t][j][r] = 0.f;

    auto issue = [&](int s, int kt) {
        cp16(&stA[s][saOfs], Ag + kt * 16);
        cp16(&fgB[s][tid], Bg + (size_t)kt * 256);
        asm volatile("cp.async.commit_group;");
    };

    issue(0, 0); issue(1, 1); issue(2, 2);

    for (int c = 0; c < nc; c++) {
        if (c <= nc - 3)      asm volatile("cp.async.wait_group 2;");
        else if (c == nc - 2) asm volatile("cp.async.wait_group 1;");
        else                  asm volatile("cp.async.wait_group 0;");
        __syncthreads();
        if (c + 3 < nc) issue((c + 3) & 3, c + 3);

        const int buf = c & 3;
        unsigned a[2][4];
        #pragma unroll
        for (int t = 0; t < 2; t++) {
            const __half* st = &stA[buf][(wm + t * 16 + g) * 24 + 2 * q];
            a[t][0] = *reinterpret_cast<const unsigned*>(st);
            a[t][1] = *reinterpret_cast<const unsigned*>(st + 8 * 24);
            a[t][2] = *reinterpret_cast<const unsigned*>(st + 8);
            a[t][3] = *reinterpret_cast<const unsigned*>(st + 8 * 24 + 8);
        }
        #pragma unroll
        for (int jp = 0; jp < 4; jp++) {
            const uint4 v = fgB[buf][((warp & 1) * 4 + jp) * 32 + lane];
            mmah(acc[0][jp * 2    ], a[0], v.x, v.y);
            mmah(acc[0][jp * 2 + 1], a[0], v.z, v.w);
            mmah(acc[1][jp * 2    ], a[1], v.x, v.y);
            mmah(acc[1][jp * 2 + 1], a[1], v.z, v.w);
        }
    }

    hgemm_epilogue<MODE, OUTH>(acc, bias, R, Cout, bm0, bn0, wm, wn, g, q, N);
}

// ---------------------------------------------------------------------------
// hgemm32: K-chunk 32, 3-stage (FFN2, K=3072). CTA 128x128.
// ---------------------------------------------------------------------------
#define ASTRIDE 40
#define HG_SMEM (3*(128*ASTRIDE*2) + 3*512*16)   // 55296 B

template<int MODE, bool OUTH>
__global__ __launch_bounds__(256, 2) void hgemm32_kernel(
    const __half* __restrict__ A, const __half* __restrict__ Wpk,
    const float* __restrict__ bias, const float* __restrict__ R,
    void* __restrict__ Cout, int K, int N)
{
    extern __shared__ char hsm[];
    __half* stA = (__half*)hsm;
    uint4*  fgB = (uint4*)(hsm + 3 * 128 * ASTRIDE * 2);

    const int tid  = threadIdx.x;
    const int lane = tid & 31;
    const int warp = tid >> 5;
    const int g    = lane >> 2;
    const int q    = lane & 3;
    const int bm0  = blockIdx.y * 128;
    const int bn0  = blockIdx.x * 128;
    const int wn   = (warp & 1) * 64;
    const int wm   = (warp >> 1) * 32;

    const int nc = K / 32;
    const __half* Ag = A + (size_t)(bm0 + (tid >> 2)) * K + (tid & 3) * 8;
    const uint4*  Bg = reinterpret_cast<const uint4*>(Wpk)
                       + (size_t)blockIdx.x * (K / 16) * 256 + tid;
    const int saOfs = (tid >> 2) * ASTRIDE + (tid & 3) * 8;

    float acc[2][8][4];
    #pragma unroll
    for (int t = 0; t < 2; t++)
        #pragma unroll
        for (int j = 0; j < 8; j++)
            #pragma unroll
            for (int r = 0; r < 4; r++) acc[t][j][r] = 0.f;

    auto issue = [&](int s, int kt) {
        __half* sa = stA + s * (128 * ASTRIDE);
        cp16(sa + saOfs,                Ag + kt * 32);
        cp16(sa + saOfs + 64 * ASTRIDE, Ag + (size_t)64 * K + kt * 32);
        uint4* fb = fgB + s * 512;
        cp16(fb + tid,       Bg + (size_t)kt * 512);
        cp16(fb + tid + 256, Bg + (size_t)kt * 512 + 256);
        asm volatile("cp.async.commit_group;");
    };

    issue(0, 0); issue(1, 1);

    for (int c = 0; c < nc; c++) {
        if (c < nc - 1) asm volatile("cp.async.wait_group 1;");
        else            asm volatile("cp.async.wait_group 0;");
        __syncthreads();
        if (c + 2 < nc) {
            int s = c + 2; s -= (s >= 3) ? ((s / 3) * 3) : 0;
            issue(s, c + 2);
        }

        int buf = c; buf -= (buf / 3) * 3;
        const __half* sa = stA + buf * (128 * ASTRIDE);
        const uint4*  fb = fgB + buf * 512;

        #pragma unroll
        for (int s = 0; s < 2; s++) {
            unsigned a[2][4];
            #pragma unroll
            for (int t = 0; t < 2; t++) {
                const __half* st = sa + (wm + t * 16 + g) * ASTRIDE + s * 16 + 2 * q;
                a[t][0] = *reinterpret_cast<const unsigned*>(st);
                a[t][1] = *reinterpret_cast<const unsigned*>(st + 8 * ASTRIDE);
                a[t][2] = *reinterpret_cast<const unsigned*>(st + 8);
                a[t][3] = *reinterpret_cast<const unsigned*>(st + 8 * ASTRIDE + 8);
            }
            #pragma unroll
            for (int jp = 0; jp < 4; jp++) {
                const uint4 v = fb[s * 256 + ((warp & 1) * 4 + jp) * 32 + lane];
                mmah(acc[0][jp * 2    ], a[0], v.x, v.y);
                mmah(acc[0][jp * 2 + 1], a[0], v.z, v.w);
                mmah(acc[1][jp * 2    ], a[1], v.x, v.y);
                mmah(acc[1][jp * 2 + 1], a[1], v.z, v.w);
            }
        }
    }

    hgemm_epilogue<MODE, OUTH>(acc, bias, R, Cout, bm0, bn0, wm, wn, g, q, N);
}

// ---------------------------------------------------------------------------
// fused: atom-encoder SGEMM (x<6) + structural bias (fp16) + token fill
// ---------------------------------------------------------------------------
#define BM 128
#define BN 128
#define BK 8
#define TM 8
#define TN 8
#define XTRA 1538u

__global__ __launch_bounds__(256) void atom_fused_kernel(
    const float* __restrict__ A, const float* __restrict__ W,
    const float* __restrict__ bias_b, float* __restrict__ C,
    const int* __restrict__ len_spd, const float* __restrict__ spd_emb,
    const float* __restrict__ virt, const float* __restrict__ gt,
    __half* __restrict__ bias)
{
    const int tid = threadIdx.x;

    if (blockIdx.x >= 6) {
        const size_t idx = ((size_t)(blockIdx.x - 6) * 64 + blockIdx.y) * 256 + tid;
        const size_t btot = (size_t)BATCH * NHEAD * NTOT * NTOT;
        if (idx < btot) {
            const int j = (int)(idx & 255);
            const int i = (int)((idx >> 8) & 255);
            const int hh = (int)((idx >> 16) % NHEAD);
            const int b = (int)(idx / ((size_t)NHEAD * NTOT * NTOT));
            float v;
            if (i == 0 || j == 0) {
                v = virt[hh];
            } else {
                const int lsp = len_spd[((size_t)b * NTOK + (i - 1)) * NTOK + (j - 1)];
                v = (lsp == 0) ? 0.f : spd_emb[lsp * NHEAD + hh];
            }
            bias[idx] = __float2half_rn(v);
        } else {
            const size_t r = idx - btot;
            if (r < (size_t)BATCH * HID) {
                const int b = (int)(r / HID), t = (int)(r % HID);
                C[(size_t)b * NTOT * HID + t] = gt[t];
            }
        }
        return;
    }

    __shared__ float As[BK][BM];
    __shared__ float Bs[BK][BN];

    const int bm0 = blockIdx.y * BM;
    const int bn0 = blockIdx.x * BN;
    const int tx = tid & 15;
    const int ty = tid >> 4;

    float acc[TM][TN];
    #pragma unroll
    for (int i = 0; i < TM; i++)
        #pragma unroll
        for (int j = 0; j < TN; j++) acc[i][j] = 0.f;

    const int arow = tid >> 1;
    const int acol = (tid & 1) * 4;
    const int brow = tid >> 5;
    const int bcol = (tid & 31) * 4;

    for (int k0 = 0; k0 < DIN; k0 += BK) {
        float4 av;
        const int gm = bm0 + arow;
        if (gm < MATOM)
            av = *reinterpret_cast<const float4*>(A + (size_t)gm * DIN + k0 + acol);
        else
            av = make_float4(0.f, 0.f, 0.f, 0.f);
        As[acol + 0][arow] = av.x;
        As[acol + 1][arow] = av.y;
        As[acol + 2][arow] = av.z;
        As[acol + 3][arow] = av.w;

        const float4 bv = *reinterpret_cast<const float4*>(
            W + (size_t)(k0 + brow) * HID + bn0 + bcol);
        *reinterpret_cast<float4*>(&Bs[brow][bcol]) = bv;

        __syncthreads();
        #pragma unroll
        for (int k = 0; k < BK; k++) {
            float af[TM], bf[TN];
            #pragma unroll
            for (int i = 0; i < TM; i++) af[i] = As[k][ty * TM + i];
            #pragma unroll
            for (int j = 0; j < TN; j++) bf[j] = Bs[k][tx * TN + j];
            #pragma unroll
            for (int i = 0; i < TM; i++)
                #pragma unroll
                for (int j = 0; j < TN; j++)
                    acc[i][j] = fmaf(af[i], bf[j], acc[i][j]);
        }
        __syncthreads();
    }

    #pragma unroll
    for (int i = 0; i < TM; i++) {
        const int m = bm0 + ty * TM + i;
        if (m >= MATOM) continue;
        const size_t orow = (size_t)m + (size_t)(m / NTOK) + 1;
        #pragma unroll
        for (int j = 0; j < TN; j++) {
            const int nn = bn0 + tx * TN + j;
            C[orow * HID + nn] = acc[i][j] + bias_b[nn];
        }
    }
}

// ---------------------------------------------------------------------------
// LayerNorm v2: warp-per-row, grid-stride, shfl-only reductions, no smem.
// ---------------------------------------------------------------------------
#define LN_BLOCKS 256

template<bool OUTH>
__global__ __launch_bounds__(256) void ln_kernel(
    const float* __restrict__ X, const float* __restrict__ w,
    const float* __restrict__ b, void* __restrict__ Yout)
{
    const int lane = threadIdx.x & 31;
    const int gw0  = blockIdx.x * 8 + (threadIdx.x >> 5);

    for (int row = gw0; row < MROWS; row += LN_BLOCKS * 8) {
        const float* x = X + (size_t)row * HID;
        float v[24];
        float s = 0.f;
        #pragma unroll
        for (int i = 0; i < 24; i++) { v[i] = x[lane + 32 * i]; s += v[i]; }
        #pragma unroll
        for (int o = 16; o > 0; o >>= 1) s += __shfl_xor_sync(~0u, s, o);
        const float mu = s * (1.f / HID);

        float s2 = 0.f;
        #pragma unroll
        for (int i = 0; i < 24; i++) { const float d = v[i] - mu; s2 = fmaf(d, d, s2); }
        #pragma unroll
        for (int o = 16; o > 0; o >>= 1) s2 += __shfl_xor_sync(~0u, s2, o);
        const float inv = rsqrtf(s2 * (1.f / HID) + 1e-5f);

        if (OUTH) {
            __half* Y = (__half*)Yout + (size_t)row * HID;
            #pragma unroll
            for (int i = 0; i < 24; i++) {
                const int c = lane + 32 * i;
                Y[c] = __float2half_rn((v[i] - mu) * inv * w[c] + b[c]);
            }
        } else {
            float* Y = (float*)Yout + (size_t)row * HID;
            #pragma unroll
            for (int i = 0; i < 24; i++) {
                const int c = lane + 32 * i;
                Y[c] = (v[i] - mu) * inv * w[c] + b[c];
            }
        }
    }
}

// ---------------------------------------------------------------------------
// Attention v5: two-chunk online softmax (exact), peak regs ~120 -> 2 CTA/SM.
// ---------------------------------------------------------------------------
#define KT_S 264
#define VT_S 72
#define QS_S 36
#define ATTN_SMEM ((32*KT_S + 128*VT_S + 128*QS_S) * 4)

__global__ __launch_bounds__(256, 2) void attn_kernel(
    const __half* __restrict__ Q, const __half* __restrict__ K,
    const __half* __restrict__ V, const __half* __restrict__ bias,
    __half* __restrict__ O)
{
    extern __shared__ char smraw[];
    __half2* KT = (__half2*)smraw;
    __half2* VT = KT + 32 * KT_S;
    __half2* QS = VT + 128 * VT_S;

    const int h = blockIdx.x, b = blockIdx.y;
    const int tid = threadIdx.x, lane = tid & 31, warp = tid >> 5;
    const int g = lane >> 2, q = lane & 3;
    const size_t base = (size_t)b * NTOT * HID + (size_t)h * HDIM;

    for (int i = tid; i < 8192; i += 256) {
        const int n = i >> 5, k2 = i & 31;
        KT[k2 * KT_S + n] =
            reinterpret_cast<const __half2*>(K + base + (size_t)n * HID)[k2];
    }
    for (int i = tid; i < 8192; i += 256) {
        const int t2 = i >> 6, d = i & 63;
        VT[t2 * VT_S + d] = __halves2half2(V[base + (size_t)(2 * t2) * HID + d],
                                           V[base + (size_t)(2 * t2 + 1) * HID + d]);
    }

    const __half* bb = bias + (((size_t)b * NHEAD + h) * NTOT) * NTOT;

    for (int pass = 0; pass < 2; pass++) {
        __syncthreads();
        for (int i = tid; i < 4096; i += 256) {
            const int r = i >> 5, k2 = i & 31;
            QS[r * QS_S + k2] = reinterpret_cast<const __half2*>(
                Q + base + (size_t)(pass * 128 + r) * HID)[k2];
        }
        __syncthreads();

        const int r0 = warp * 16;
        const int qi0 = pass * 128 + r0 + g;
        const int qi1 = qi0 + 8;

        float av[8][4];
        #pragma unroll
        for (int j = 0; j < 8; j++) {
            av[j][0] = av[j][1] = av[j][2] = av[j][3] = 0.f;
        }
        float m0 = -1e30f, m1 = -1e30f, s0 = 0.f, s1 = 0.f;

        #pragma unroll
        for (int ch = 0; ch < 2; ch++) {
            // S chunk: keys [ch*128, ch*128+128)
            float sc[16][4];
            #pragma unroll
            for (int j = 0; j < 16; j++) {
                sc[j][0] = sc[j][1] = sc[j][2] = sc[j][3] = 0.f;
            }
            #pragma unroll
            for (int kt = 0; kt < 4; kt++) {
                unsigned a[4];
                a[0] = *reinterpret_cast<const unsigned*>(&QS[(r0 + g    ) * QS_S + q + 8 * kt]);
                a[1] = *reinterpret_cast<const unsigned*>(&QS[(r0 + g + 8) * QS_S + q + 8 * kt]);
                a[2] = *reinterpret_cast<const unsigned*>(&QS[(r0 + g    ) * QS_S + q + 4 + 8 * kt]);
                a[3] = *reinterpret_cast<const unsigned*>(&QS[(r0 + g + 8) * QS_S + q + 4 + 8 * kt]);
                #pragma unroll
                for (int j = 0; j < 16; j++) {
                    const int col = ch * 128 + j * 8 + g;
                    const unsigned b0 = *reinterpret_cast<const unsigned*>(
                        &KT[(8 * kt + q    ) * KT_S + col]);
                    const unsigned b1 = *reinterpret_cast<const unsigned*>(
                        &KT[(8 * kt + 4 + q) * KT_S + col]);
                    mmah(sc[j], a, b0, b1);
                }
            }

            // bias + chunk max
            const __half* b0r = bb + (size_t)qi0 * NTOT + ch * 128;
            const __half* b1r = bb + (size_t)qi1 * NTOT + ch * 128;
            float cm0 = -1e30f, cm1 = -1e30f;
            #pragma unroll
            for (int j = 0; j < 16; j++) {
                const float2 bg0 = __half22float2(
                    *reinterpret_cast<const __half2*>(&b0r[j * 8 + 2 * q]));
                const float2 bg1 = __half22float2(
                    *reinterpret_cast<const __half2*>(&b1r[j * 8 + 2 * q]));
                sc[j][0] = sc[j][0] * 0.125f + bg0.x;
                sc[j][1] = sc[j][1] * 0.125f + bg0.y;
                sc[j][2] = sc[j][2] * 0.125f + bg1.x;
                sc[j][3] = sc[j][3] * 0.125f + bg1.y;
                cm0 = fmaxf(cm0, fmaxf(sc[j][0], sc[j][1]));
                cm1 = fmaxf(cm1, fmaxf(sc[j][2], sc[j][3]));
            }
            cm0 = fmaxf(cm0, __shfl_xor_sync(~0u, cm0, 1));
            cm0 = fmaxf(cm0, __shfl_xor_sync(~0u, cm0, 2));
            cm1 = fmaxf(cm1, __shfl_xor_sync(~0u, cm1, 1));
            cm1 = fmaxf(cm1, __shfl_xor_sync(~0u, cm1, 2));

            // online merge (first chunk: exp(-1e30 - nm) == 0 handles init)
            const float nm0 = fmaxf(m0, cm0), nm1 = fmaxf(m1, cm1);
            const float r0f = __expf(m0 - nm0), r1f = __expf(m1 - nm1);
            s0 *= r0f; s1 *= r1f;
            #pragma unroll
            for (int j = 0; j < 8; j++) {
                av[j][0] *= r0f; av[j][1] *= r0f;
                av[j][2] *= r1f; av[j][3] *= r1f;
            }
            m0 = nm0; m1 = nm1;

            // exp + AV interleaved (P lives 4 regs)
            #pragma unroll
            for (int kt = 0; kt < 8; kt++) {
                const float e00 = __expf(sc[2 * kt][0] - m0);
                const float e01 = __expf(sc[2 * kt][1] - m0);
                const float e10 = __expf(sc[2 * kt][2] - m1);
                const float e11 = __expf(sc[2 * kt][3] - m1);
                const float f00 = __expf(sc[2 * kt + 1][0] - m0);
                const float f01 = __expf(sc[2 * kt + 1][1] - m0);
                const float f10 = __expf(sc[2 * kt + 1][2] - m1);
                const float f11 = __expf(sc[2 * kt + 1][3] - m1);
                s0 += e00 + e01 + f00 + f01;
                s1 += e10 + e11 + f10 + f11;
                const __half2 pa0h = __floats2half2_rn(e00, e01);
                const __half2 pa1h = __floats2half2_rn(e10, e11);
                const __half2 pb0h = __floats2half2_rn(f00, f01);
                const __half2 pb1h = __floats2half2_rn(f10, f11);
                const unsigned a[4] = {
                    *reinterpret_cast<const unsigned*>(&pa0h),
                    *reinterpret_cast<const unsigned*>(&pa1h),
                    *reinterpret_cast<const unsigned*>(&pb0h),
                    *reinterpret_cast<const unsigned*>(&pb1h) };
                const int vrow = 64 * ch + 8 * kt;
                #pragma unroll
                for (int j = 0; j < 8; j++) {
                    const unsigned vb0 = *reinterpret_cast<const unsigned*>(
                        &VT[(vrow + q    ) * VT_S + j * 8 + g]);
                    const unsigned vb1 = *reinterpret_cast<const unsigned*>(
                        &VT[(vrow + 4 + q) * VT_S + j * 8 + g]);
                    mmah(av[j], a, vb0, vb1);
                }
            }
        }

        s0 += __shfl_xor_sync(~0u, s0, 1); s0 += __shfl_xor_sync(~0u, s0, 2);
        s1 += __shfl_xor_sync(~0u, s1, 1); s1 += __shfl_xor_sync(~0u, s1, 2);
        const float i0 = 1.f / s0, i1 = 1.f / s1;

        __half2* O0 = reinterpret_cast<__half2*>(O + base + (size_t)qi0 * HID);
        __half2* O1 = reinterpret_cast<__half2*>(O + base + (size_t)qi1 * HID);
        #pragma unroll
        for (int j = 0; j < 8; j++) {
            O0[j * 4 + q] = __floats2half2_rn(av[j][0] * i0, av[j][1] * i0);
            O1[j * 4 + q] = __floats2half2_rn(av[j][2] * i1, av[j][3] * i1);
        }
    }
}

// ---------------------------------------------------------------------------
// Launch
// ---------------------------------------------------------------------------
extern "C" void kernel_launch(void* const* d_in, const int* in_sizes, int n_in,
                              void* d_out, int out_size)
{
    const float* x          = (const float*)d_in[0];
    const int*   len_spd    = (const int*)  d_in[1];
    const float* atom_W     = (const float*)d_in[2];
    const float* atom_b     = (const float*)d_in[3];
    const float* spd_emb    = (const float*)d_in[4];
    const float* graph_tok  = (const float*)d_in[5];
    const float* virt_dist  = (const float*)d_in[6];
    const float* ln1_w      = (const float*)d_in[7];
    const float* ln1_b      = (const float*)d_in[8];
    const float* Wq         = (const float*)d_in[9];
    const float* bq         = (const float*)d_in[10];
    const float* Wk         = (const float*)d_in[11];
    const float* bk         = (const float*)d_in[12];
    const float* Wv         = (const float*)d_in[13];
    const float* bv         = (const float*)d_in[14];
    const float* Wo         = (const float*)d_in[15];
    const float* bo         = (const float*)d_in[16];
    const float* ln2_w      = (const float*)d_in[17];
    const float* ln2_b      = (const float*)d_in[18];
    const float* W1         = (const float*)d_in[19];
    const float* b1         = (const float*)d_in[20];
    const float* W2         = (const float*)d_in[21];
    const float* b2         = (const float*)d_in[22];
    const float* fln_w      = (const float*)d_in[23];
    const float* fln_b      = (const float*)d_in[24];

    float *h;
    __half *yh, *qh, *kh, *vh, *oh, *fh, *wt, *bias;
    cudaGetSymbolAddress((void**)&h,    g_h);
    cudaGetSymbolAddress((void**)&yh,   g_yh);
    cudaGetSymbolAddress((void**)&qh,   g_qh);
    cudaGetSymbolAddress((void**)&kh,   g_kh);
    cudaGetSymbolAddress((void**)&vh,   g_vh);
    cudaGetSymbolAddress((void**)&oh,   g_oh);
    cudaGetSymbolAddress((void**)&fh,   g_fh);
    cudaGetSymbolAddress((void**)&bias, g_bias);
    cudaGetSymbolAddress((void**)&wt,   g_wt);

    cudaFuncSetAttribute(attn_kernel, cudaFuncAttributeMaxDynamicSharedMemorySize,
                         (int)ATTN_SMEM);
    cudaFuncSetAttribute(hgemm32_kernel<EP_BIAS_RES, false>,
                         cudaFuncAttributeMaxDynamicSharedMemorySize, HG_SMEM);

    const size_t szQ = (size_t)HID * HID, szF = (size_t)HID * FFN;

    const dim3 gQKV(18, MROWS / 128);
    const dim3 gHID(HID / 128, MROWS / 128);
    const dim3 gFFN(FFN / 128, MROWS / 128);

    // L1: repack QKVO weights (all layers)
    repack_qkvo_kernel<<<dim3((unsigned)(szQ / 2 / 256), 1, 4 * NLAYER), 256>>>(
        Wq, Wk, Wv, Wo, (__half2*)wt);
    // L2: fused atom encoder + bias(fp16) + token fill
    atom_fused_kernel<<<dim3(6 + XTRA, 64), 256>>>(
        x, atom_W, atom_b, h, len_spd, spd_emb, virt_dist, graph_tok, bias);
    // L3: ln1 layer 0
    ln_kernel<true><<<LN_BLOCKS, 256>>>(h, ln1_w, ln1_b, yh);
    // L4: QKV fused hgemm16 layer 0  <-- ncu capture slot
    hgemm16_kernel<EP_BIAS, true, true><<<gQKV, 256>>>(
        yh, wt, bq, bk, bv, nullptr, qh, kh, vh, HID, HID);
    // L5: repack W1/W2
    repack_w12_kernel<<<dim3((unsigned)(szF / 2 / 256), 1, 2 * NLAYER), 256>>>(
        W1, W2, (__half2*)wt);

    for (int l = 0; l < NLAYER; l++) {
        const size_t bofs  = (size_t)l * HID;
        const size_t b1ofs = (size_t)l * FFN;
        __half* wl = wt + (size_t)l * WT_L;

        if (l > 0) {
            ln_kernel<true><<<LN_BLOCKS, 256>>>(h, ln1_w + bofs, ln1_b + bofs, yh);
            hgemm16_kernel<EP_BIAS, true, true><<<gQKV, 256>>>(
                yh, wl, bq + bofs, bk + bofs, bv + bofs, nullptr,
                qh, kh, vh, HID, HID);
        }

        attn_kernel<<<dim3(NHEAD, BATCH), 256, ATTN_SMEM>>>(qh, kh, vh, bias, oh);

        hgemm16_kernel<EP_BIAS_RES, false, false><<<gHID, 256>>>(
            oh, wl + 3 * (size_t)WT_QKVO, bo + bofs, nullptr, nullptr, h,
            h, nullptr, nullptr, HID, HID);

        ln_kernel<true><<<LN_BLOCKS, 256>>>(h, ln2_w + bofs, ln2_b + bofs, yh);

        hgemm16_kernel<EP_BIAS_GELU, true, false><<<gFFN, 256>>>(
            yh, wl + 4 * (size_t)WT_QKVO, b1 + b1ofs, nullptr, nullptr, nullptr,
            fh, nullptr, nullptr, HID, FFN);
        hgemm32_kernel<EP_BIAS_RES, false><<<gHID, 256, HG_SMEM>>>(
            fh, wl + 4 * (size_t)WT_QKVO + szF, b2 + bofs, h,
            h, FFN, HID);
    }

    ln_kernel<false><<<LN_BLOCKS, 256>>>(h, fln_w, fln_b, d_out);
}